// round 14
// baseline (speedup 1.0000x reference)
#include <cuda_runtime.h>
#include <stdint.h>
#include <math.h>

#define BATCH 4
#define TSEQ  1705
#define CEMB  768
#define NHEAD 12
#define HDIM  64
#define MROWS (BATCH*TSEQ)          /* 6820 */
#define KTILES ((TSEQ+63)/64)       /* 27   */
#define SEG1 9                      /* L+1 */
#define SEG2 137                    /* L+1 + L*PT */
#define SAQ 20                      /* A smem row stride: bijective mod 32 */
#define SBQ 136                     /* B smem row stride */
#define QSCALE 0.18033688011112042f /* 0.125 * log2(e): base-2 softmax domain */

// Scratch (static device arrays — no runtime allocation)
__device__ float g_q[(size_t)BATCH*NHEAD*TSEQ*HDIM];
__device__ float g_k[(size_t)BATCH*NHEAD*TSEQ*HDIM];
__device__ float g_v[(size_t)BATCH*NHEAD*TSEQ*HDIM];
__device__ __align__(128) unsigned g_x32[(size_t)MROWS*CEMB];
__device__ __align__(128) unsigned g_y32[(size_t)MROWS*CEMB];
__device__ __align__(128) unsigned g_wa32[(size_t)CEMB*3*CEMB];
__device__ __align__(128) unsigned g_wp32[(size_t)CEMB*CEMB];
__device__ int4 g_lim[TSEQ];        // per-row prefix limits: (a, t, i, 0)

// ---------------------------------------------------------------------------
// helpers
// ---------------------------------------------------------------------------
__device__ __forceinline__ unsigned f2tf32(float x) {
    unsigned r;
    asm("cvt.rna.tf32.f32 %0, %1;" : "=r"(r) : "f"(x));
    return r;
}
__device__ __forceinline__ float ex2f(float x) {
    float r;
    asm("ex2.approx.f32 %0, %1;" : "=f"(r) : "f"(x));
    return r;
}
__device__ __forceinline__ void mma_tf32(float* c, const unsigned* a, const unsigned* b) {
    asm volatile(
        "mma.sync.aligned.m16n8k8.row.col.f32.tf32.tf32.f32 "
        "{%0,%1,%2,%3}, {%4,%5,%6,%7}, {%8,%9}, {%0,%1,%2,%3};"
        : "+f"(c[0]), "+f"(c[1]), "+f"(c[2]), "+f"(c[3])
        : "r"(a[0]), "r"(a[1]), "r"(a[2]), "r"(a[3]), "r"(b[0]), "r"(b[1]));
}

// ---------------------------------------------------------------------------
// Elementwise f32 -> tf32-bits pre-conversion (dst = device symbol via sel)
// ---------------------------------------------------------------------------
__global__ void cvt_tf32(const float* __restrict__ src, int sel, int n4) {
    unsigned* dst = (sel == 0) ? g_x32 : (sel == 1) ? g_wa32 : g_wp32;
    int i = blockIdx.x * blockDim.x + threadIdx.x;
    if (i >= n4) return;
    float4 v = *(const float4*)&src[i * 4];
    uint4 o;
    o.x = f2tf32(v.x); o.y = f2tf32(v.y);
    o.z = f2tf32(v.z); o.w = f2tf32(v.w);
    *(uint4*)&dst[i * 4] = o;
}

// ---------------------------------------------------------------------------
// Row prefix limits (mask = union of 3 per-row segment prefixes).
// ---------------------------------------------------------------------------
__global__ void row_limits(const unsigned char* __restrict__ raw) {
    const int q = blockIdx.x;
    const int tid = threadIdx.x;
    const unsigned char b0 = raw[0], b1 = raw[1];
    const int mode = (b1 == 1) ? 0 : (b0 == 1) ? 1 : 2;

    int c0 = 0, c1 = 0, c2 = 0;
    for (int k = tid; k < TSEQ; k += 256) {
        size_t idx = (size_t)q * TSEQ + k;
        int v;
        if (mode == 0)      v = raw[idx] != 0;
        else if (mode == 1) v = ((const int*)raw)[idx] != 0;
        else                v = ((const float*)raw)[idx] != 0.0f;
        if (k < SEG1)      c0 += v;
        else if (k < SEG2) c1 += v;
        else               c2 += v;
    }
    __shared__ int s0, s1, s2;
    if (tid == 0) { s0 = 0; s1 = 0; s2 = 0; }
    __syncthreads();
#pragma unroll
    for (int off = 16; off; off >>= 1) {
        c0 += __shfl_xor_sync(0xffffffffu, c0, off);
        c1 += __shfl_xor_sync(0xffffffffu, c1, off);
        c2 += __shfl_xor_sync(0xffffffffu, c2, off);
    }
    if ((tid & 31) == 0) {
        atomicAdd(&s0, c0); atomicAdd(&s1, c1); atomicAdd(&s2, c2);
    }
    __syncthreads();
    if (tid == 0) g_lim[q] = make_int4(s0, SEG1 + s1, SEG2 + s2, 0);
}

// ---------------------------------------------------------------------------
// cp.async-pipelined tf32 GEMM (R11, known good — unchanged).
// ---------------------------------------------------------------------------
template<bool SCATTER>
__global__ __launch_bounds__(256) void gemm_cp(float* __restrict__ out) {
    const unsigned* __restrict__ A = SCATTER ? g_x32 : g_y32;
    const unsigned* __restrict__ W = SCATTER ? g_wa32 : g_wp32;
    constexpr int LDB = SCATTER ? 3 * CEMB : CEMB;
    constexpr int ASTG = 128 * SAQ;
    constexpr int BSTG = 16 * SBQ;

    extern __shared__ unsigned smg[];
    unsigned* As0 = smg;
    unsigned* Bs0 = smg + 3 * ASTG;

    const int m0 = blockIdx.y * 128;
    const int n0 = blockIdx.x * 128;
    const int tid = threadIdx.x;
    const int lane = tid & 31;
    const int warp = tid >> 5;
    const int wm = (warp & 3) * 32;
    const int wn = (warp >> 2) * 64;
    const int fr = lane >> 2;
    const int fc = lane & 3;

    float acc[2][8][4];
#pragma unroll
    for (int mf = 0; mf < 2; mf++)
#pragma unroll
        for (int nf = 0; nf < 8; nf++)
#pragma unroll
            for (int r = 0; r < 4; r++) acc[mf][nf][r] = 0.f;

#define STAGE(kt_, buf_)                                                       \
    {                                                                          \
        const int k0_ = (kt_) * 16;                                            \
        _Pragma("unroll")                                                      \
        for (int u = 0; u < 2; u++) {                                          \
            int ia = tid + u * 256;                                            \
            int arow = ia >> 2, ac4 = (ia & 3) * 4;                            \
            int gm = m0 + arow;                                                \
            int apred = (gm < MROWS) ? 16 : 0;                                 \
            int gmc = gm < MROWS ? gm : MROWS - 1;                             \
            const unsigned* asrc = &A[(size_t)gmc * CEMB + k0_ + ac4];         \
            unsigned adst = (unsigned)__cvta_generic_to_shared(                \
                                &As0[(buf_) * ASTG + arow * SAQ + ac4]);       \
            asm volatile("cp.async.cg.shared.global [%0], [%1], 16, %2;"       \
                         :: "r"(adst), "l"(asrc), "r"(apred));                 \
            int ib = tid + u * 256;                                            \
            int brow = ib >> 5, bc4 = (ib & 31) * 4;                           \
            const unsigned* bsrc = &W[(size_t)(k0_ + brow) * LDB + n0 + bc4];  \
            unsigned bdst = (unsigned)__cvta_generic_to_shared(                \
                                &Bs0[(buf_) * BSTG + brow * SBQ + bc4]);       \
            asm volatile("cp.async.cg.shared.global [%0], [%1], 16;"           \
                         :: "r"(bdst), "l"(bsrc));                             \
        }                                                                      \
    }

    STAGE(0, 0);
    asm volatile("cp.async.commit_group;");
    STAGE(1, 1);
    asm volatile("cp.async.commit_group;");

    const int NK = CEMB / 16;  // 48
    for (int kt = 0; kt < NK; kt++) {
        asm volatile("cp.async.wait_group 1;");
        __syncthreads();

        if (kt + 2 < NK) STAGE(kt + 2, (kt + 2) % 3);
        asm volatile("cp.async.commit_group;");

        const unsigned* Asb = &As0[(kt % 3) * ASTG];
        const unsigned* Bsb = &Bs0[(kt % 3) * BSTG];
#pragma unroll
        for (int ks = 0; ks < 2; ks++) {
            const int kb = ks * 8;
            unsigned af[2][4], bf[8][2];
#pragma unroll
            for (int mf = 0; mf < 2; mf++) {
                af[mf][0] = Asb[(wm + mf * 16 + fr)     * SAQ + kb + fc];
                af[mf][1] = Asb[(wm + mf * 16 + fr + 8) * SAQ + kb + fc];
                af[mf][2] = Asb[(wm + mf * 16 + fr)     * SAQ + kb + fc + 4];
                af[mf][3] = Asb[(wm + mf * 16 + fr + 8) * SAQ + kb + fc + 4];
            }
#pragma unroll
            for (int nf = 0; nf < 8; nf++) {
                bf[nf][0] = Bsb[(kb + fc)     * SBQ + wn + nf * 8 + fr];
                bf[nf][1] = Bsb[(kb + fc + 4) * SBQ + wn + nf * 8 + fr];
            }
#pragma unroll
            for (int mf = 0; mf < 2; mf++)
#pragma unroll
                for (int nf = 0; nf < 8; nf++)
                    mma_tf32(acc[mf][nf], af[mf], bf[nf]);
        }
    }
#undef STAGE

    if (SCATTER) {
#pragma unroll
        for (int mf = 0; mf < 2; mf++)
#pragma unroll
            for (int nf = 0; nf < 8; nf++)
#pragma unroll
                for (int rg = 0; rg < 4; rg++) {
                    int m = m0 + wm + mf * 16 + fr + ((rg >= 2) ? 8 : 0);
                    if (m >= MROWS) continue;
                    int n = n0 + wn + nf * 8 + 2 * fc + (rg & 1);
                    int bb = m / TSEQ;
                    int t  = m - bb * TSEQ;
                    int which = n / CEMB;
                    int rem = n - which * CEMB;
                    int h = rem >> 6, d = rem & 63;
                    float* dst = (which == 0) ? g_q : (which == 1) ? g_k : g_v;
                    dst[((((size_t)bb * NHEAD + h) * TSEQ + t) << 6) + d] = acc[mf][nf][rg];
                }
    } else {
#pragma unroll
        for (int mf = 0; mf < 2; mf++)
#pragma unroll
            for (int nf = 0; nf < 8; nf++) {
                int n  = n0 + wn + nf * 8 + 2 * fc;
                int m1 = m0 + wm + mf * 16 + fr;
                if (m1 < MROWS)
                    *(float2*)&out[(size_t)m1 * CEMB + n] =
                        make_float2(acc[mf][nf][0], acc[mf][nf][1]);
                int m2 = m1 + 8;
                if (m2 < MROWS)
                    *(float2*)&out[(size_t)m2 * CEMB + n] =
                        make_float2(acc[mf][nf][2], acc[mf][nf][3]);
            }
    }
}

// ---------------------------------------------------------------------------
// Flash attention v5 = R11 v4 + heavy-first qt ordering + base-2 softmax.
// qt = KTILES-1-blockIdx.x: heaviest blocks (largest ktmax) launch first,
// minimizing the multi-wave tail. Softmax in log2 domain (Q pre-scaled by
// 0.125*log2e; bare ex2.approx replaces __expf — same math, fewer FMULs).
// ---------------------------------------------------------------------------
__global__ __launch_bounds__(128) void attn_v5() {
    extern __shared__ float sm4[];
    float* Kbuf[2] = { sm4,                sm4 + 64 * 68 };
    float* Vbuf[2] = { sm4 + 2 * 64 * 68,  sm4 + 2 * 64 * 68 + 64 * 72 };
    __shared__ int s_ktmax;

    const int qt = (KTILES - 1) - blockIdx.x;   // heavy-first scheduling
    const int h = blockIdx.y, b = blockIdx.z;
    const int q0 = qt * 64;
    const int tid = threadIdx.x, lane = tid & 31, warp = tid >> 5;
    const int fr = lane >> 2, fc = lane & 3;
    const int ra = warp * 16 + fr, rb = ra + 8;
    const int qa = q0 + ra, qb = q0 + rb;
    const size_t bh = ((size_t)b * NHEAD + h) * TSEQ;

    int4 La = make_int4(0, 0, 0, 0), Lb = La;
    if (qa < TSEQ) La = g_lim[qa];
    if (qb < TSEQ) Lb = g_lim[qb];

    if (warp == 0) {
        int q1 = q0 + lane, q2 = q0 + 32 + lane;
        int il = 0;
        if (q1 < TSEQ) il = g_lim[q1].z;
        if (q2 < TSEQ) il = max(il, g_lim[q2].z);
#pragma unroll
        for (int off = 16; off; off >>= 1)
            il = max(il, __shfl_xor_sync(0xffffffffu, il, off));
        if (lane == 0) s_ktmax = (il + 63) >> 6;
    }

    unsigned qf[8][4];
    {
        const float* Qa = &g_q[(bh + qa) * 64];
        const float* Qb = &g_q[(bh + qb) * 64];
#pragma unroll
        for (int ks = 0; ks < 8; ks++) {
            float x0 = (qa < TSEQ) ? Qa[8 * ks + fc]     : 0.f;
            float x1 = (qb < TSEQ) ? Qb[8 * ks + fc]     : 0.f;
            float x2 = (qa < TSEQ) ? Qa[8 * ks + fc + 4] : 0.f;
            float x3 = (qb < TSEQ) ? Qb[8 * ks + fc + 4] : 0.f;
            qf[ks][0] = f2tf32(x0 * QSCALE);
            qf[ks][1] = f2tf32(x1 * QSCALE);
            qf[ks][2] = f2tf32(x2 * QSCALE);
            qf[ks][3] = f2tf32(x3 * QSCALE);
        }
    }
    __syncthreads();
    const int ktmax = s_ktmax;

#define STAGE(kt_, buf_)                                                       \
    {                                                                          \
        const int k0_ = (kt_) * 64;                                            \
        for (int i = tid; i < 64 * 16; i += 128) {                             \
            int row = i >> 4, dc = (i & 15) * 4;                               \
            int kk2 = k0_ + row;                                               \
            int pred = (kk2 < TSEQ) ? 16 : 0;                                  \
            int kk2c = kk2 < TSEQ ? kk2 : TSEQ - 1;                            \
            const float* gk = &g_k[(bh + kk2c) * 64 + dc];                     \
            const float* gv = &g_v[(bh + kk2c) * 64 + dc];                     \
            unsigned dk = (unsigned)__cvta_generic_to_shared(                  \
                              &Kbuf[buf_][row * 68 + dc]);                     \
            unsigned dv = (unsigned)__cvta_generic_to_shared(                  \
                              &Vbuf[buf_][row * 72 + dc]);                     \
            asm volatile("cp.async.cg.shared.global [%0], [%1], 16, %2;"       \
                         :: "r"(dk), "l"(gk), "r"(pred));                      \
            asm volatile("cp.async.cg.shared.global [%0], [%1], 16, %2;"       \
                         :: "r"(dv), "l"(gv), "r"(pred));                      \
        }                                                                      \
    }

    STAGE(0, 0);
    asm volatile("cp.async.commit_group;");

    float o[8][4];
#pragma unroll
    for (int nf = 0; nf < 8; nf++)
#pragma unroll
        for (int r = 0; r < 4; r++) o[nf][r] = 0.f;
    float m_a = -1e30f, m_b = -1e30f, l_a = 0.f, l_b = 0.f;

    for (int kt = 0; kt < ktmax; kt++) {
        const int k0 = kt * 64;
        const int cur = kt & 1;

        if (kt + 1 < ktmax) STAGE(kt + 1, cur ^ 1);
        asm volatile("cp.async.commit_group;");
        asm volatile("cp.async.wait_group 1;");
        __syncthreads();

        const float* Kc = Kbuf[cur];
        const float* Vc = Vbuf[cur];

        float sacc[8][4];
#pragma unroll
        for (int nf = 0; nf < 8; nf++)
#pragma unroll
            for (int r = 0; r < 4; r++) sacc[nf][r] = 0.f;
#pragma unroll
        for (int ks = 0; ks < 8; ks++) {
            int kk = ks * 8;
#pragma unroll
            for (int nf = 0; nf < 8; nf++) {
                unsigned bf[2];
                bf[0] = f2tf32(Kc[(nf * 8 + fr) * 68 + kk + fc]);
                bf[1] = f2tf32(Kc[(nf * 8 + fr) * 68 + kk + fc + 4]);
                mma_tf32(sacc[nf], qf[ks], bf);
            }
        }

        float pma = -1e30f, pmb = -1e30f;
        const bool imgonly = (k0 >= SEG2);
#pragma unroll
        for (int nf = 0; nf < 8; nf++) {
            int kc0 = k0 + nf * 8 + 2 * fc;
            int kc1 = kc0 + 1;
            int la0, la1, lb0, lb1;
            if (imgonly) {
                la0 = La.z; la1 = La.z; lb0 = Lb.z; lb1 = Lb.z;
            } else {
                la0 = kc0 < SEG1 ? La.x : kc0 < SEG2 ? La.y : La.z;
                la1 = kc1 < SEG1 ? La.x : kc1 < SEG2 ? La.y : La.z;
                lb0 = kc0 < SEG1 ? Lb.x : kc0 < SEG2 ? Lb.y : Lb.z;
                lb1 = kc1 < SEG1 ? Lb.x : kc1 < SEG2 ? Lb.y : Lb.z;
            }
            sacc[nf][0] = (kc0 < la0) ? sacc[nf][0] : -1e30f;
            sacc[nf][1] = (kc1 < la1) ? sacc[nf][1] : -1e30f;
            sacc[nf][2] = (kc0 < lb0) ? sacc[nf][2] : -1e30f;
            sacc[nf][3] = (kc1 < lb1) ? sacc[nf][3] : -1e30f;
            pma = fmaxf(pma, fmaxf(sacc[nf][0], sacc[nf][1]));
            pmb = fmaxf(pmb, fmaxf(sacc[nf][2], sacc[nf][3]));
        }
        pma = fmaxf(pma, __shfl_xor_sync(0xffffffffu, pma, 1));
        pma = fmaxf(pma, __shfl_xor_sync(0xffffffffu, pma, 2));
        pmb = fmaxf(pmb, __shfl_xor_sync(0xffffffffu, pmb, 1));
        pmb = fmaxf(pmb, __shfl_xor_sync(0xffffffffu, pmb, 2));

        const float mna = fmaxf(m_a, pma), mnb = fmaxf(m_b, pmb);
        const float ala = ex2f(m_a - mna), alb = ex2f(m_b - mnb);
        m_a = mna; m_b = mnb;

        float psa = 0.f, psb = 0.f;
#pragma unroll
        for (int nf = 0; nf < 8; nf++) {
            float p0 = sacc[nf][0] > -5e29f ? ex2f(sacc[nf][0] - mna) : 0.f;
            float p1 = sacc[nf][1] > -5e29f ? ex2f(sacc[nf][1] - mna) : 0.f;
            float p2 = sacc[nf][2] > -5e29f ? ex2f(sacc[nf][2] - mnb) : 0.f;
            float p3 = sacc[nf][3] > -5e29f ? ex2f(sacc[nf][3] - mnb) : 0.f;
            sacc[nf][0] = p0; sacc[nf][1] = p1;
            sacc[nf][2] = p2; sacc[nf][3] = p3;
            psa += p0 + p1; psb += p2 + p3;
        }
        psa += __shfl_xor_sync(0xffffffffu, psa, 1);
        psa += __shfl_xor_sync(0xffffffffu, psa, 2);
        psb += __shfl_xor_sync(0xffffffffu, psb, 1);
        psb += __shfl_xor_sync(0xffffffffu, psb, 2);
        l_a = l_a * ala + psa;
        l_b = l_b * alb + psb;
#pragma unroll
        for (int nf = 0; nf < 8; nf++) {
            o[nf][0] *= ala; o[nf][1] *= ala;
            o[nf][2] *= alb; o[nf][3] *= alb;
        }

        const unsigned FULL = 0xffffffffu;
        const int src  = fr * 4 + (fc >> 1);
        const int src2 = src + 2;
        const bool oddc = (fc & 1);
#pragma unroll
        for (int ks = 0; ks < 8; ks++) {
            float c0 = sacc[ks][0], c1 = sacc[ks][1];
            float c2 = sacc[ks][2], c3 = sacc[ks][3];
            float v00 = __shfl_sync(FULL, c0, src),  v01 = __shfl_sync(FULL, c1, src);
            float v10 = __shfl_sync(FULL, c2, src),  v11 = __shfl_sync(FULL, c3, src);
            float v20 = __shfl_sync(FULL, c0, src2), v21 = __shfl_sync(FULL, c1, src2);
            float v30 = __shfl_sync(FULL, c2, src2), v31 = __shfl_sync(FULL, c3, src2);
            unsigned pa[4];
            pa[0] = f2tf32(oddc ? v01 : v00);
            pa[1] = f2tf32(oddc ? v11 : v10);
            pa[2] = f2tf32(oddc ? v21 : v20);
            pa[3] = f2tf32(oddc ? v31 : v30);
            int kk = ks * 8;
#pragma unroll
            for (int nf = 0; nf < 8; nf++) {
                unsigned bf[2];
                bf[0] = f2tf32(Vc[(kk + fc) * 72 + nf * 8 + fr]);
                bf[1] = f2tf32(Vc[(kk + fc + 4) * 72 + nf * 8 + fr]);
                mma_tf32(o[nf], pa, bf);
            }
        }
        __syncthreads();
    }
#undef STAGE

    // Epilogue: normalize; write tf32 bits into g_y32 (consumed by proj GEMM)
    const float inva = l_a > 0.f ? 1.f / l_a : 0.f;
    const float invb = l_b > 0.f ? 1.f / l_b : 0.f;
#pragma unroll
    for (int nf = 0; nf < 8; nf++) {
        int d = h * 64 + nf * 8 + 2 * fc;
        if (qa < TSEQ) {
            uint2 t;
            t.x = f2tf32(o[nf][0] * inva);
            t.y = f2tf32(o[nf][1] * inva);
            *(uint2*)&g_y32[((size_t)b * TSEQ + qa) * CEMB + d] = t;
        }
        if (qb < TSEQ) {
            uint2 t;
            t.x = f2tf32(o[nf][2] * invb);
            t.y = f2tf32(o[nf][3] * invb);
            *(uint2*)&g_y32[((size_t)b * TSEQ + qb) * CEMB + d] = t;
        }
    }
}

// ---------------------------------------------------------------------------
extern "C" void kernel_launch(void* const* d_in, const int* in_sizes, int n_in,
                              void* d_out, int out_size) {
    const float* x  = (const float*)d_in[0];
    const float* Wa = (const float*)d_in[1];
    const float* Wp = (const float*)d_in[2];
    const unsigned char* mask_raw = (const unsigned char*)d_in[3];
    float* out = (float*)d_out;

    const int ATTN_SH = (2 * 64 * 68 + 2 * 64 * 72) * 4;            // 71680
    const int GEMM_SH = (3 * 128 * SAQ + 3 * 16 * SBQ) * 4;         // 56832
    cudaFuncSetAttribute(attn_v5, cudaFuncAttributeMaxDynamicSharedMemorySize, ATTN_SH);
    cudaFuncSetAttribute(gemm_cp<true>,  cudaFuncAttributeMaxDynamicSharedMemorySize, GEMM_SH);
    cudaFuncSetAttribute(gemm_cp<false>, cudaFuncAttributeMaxDynamicSharedMemorySize, GEMM_SH);

    row_limits<<<TSEQ, 256>>>(mask_raw);

    {
        int n4x = MROWS * CEMB / 4;
        int n4a = CEMB * 3 * CEMB / 4;
        int n4p = CEMB * CEMB / 4;
        cvt_tf32<<<(n4x + 255) / 256, 256>>>(x,  0, n4x);
        cvt_tf32<<<(n4a + 255) / 256, 256>>>(Wa, 1, n4a);
        cvt_tf32<<<(n4p + 255) / 256, 256>>>(Wp, 2, n4p);
    }

    dim3 g1(3 * CEMB / 128, (MROWS + 127) / 128);   // (18, 54)
    gemm_cp<true><<<g1, 256, GEMM_SH>>>(nullptr);

    dim3 g2(KTILES, NHEAD, BATCH);                  // (27, 12, 4)
    attn_v5<<<g2, 128, ATTN_SH>>>();

    dim3 g3(CEMB / 128, (MROWS + 127) / 128);       // (6, 54)
    gemm_cp<false><<<g3, 256, GEMM_SH>>>(out);
}

// round 15
// speedup vs baseline: 1.0880x; 1.0880x over previous
#include <cuda_runtime.h>
#include <stdint.h>
#include <math.h>

#define BATCH 4
#define TSEQ  1705
#define CEMB  768
#define NHEAD 12
#define HDIM  64
#define MROWS (BATCH*TSEQ)          /* 6820 */
#define KTILES ((TSEQ+63)/64)       /* 27   */
#define SEG1 9                      /* L+1 */
#define SEG2 137                    /* L+1 + L*PT */
#define SAQ 20                      /* A smem row stride: bijective mod 32 */
#define SBQ 136                     /* B smem row stride */

// Scratch (static device arrays — no runtime allocation)
__device__ float g_q[(size_t)BATCH*NHEAD*TSEQ*HDIM];                 // f32
__device__ __align__(128) unsigned g_k32[(size_t)BATCH*NHEAD*TSEQ*HDIM]; // tf32 bits
__device__ __align__(128) unsigned g_v32[(size_t)BATCH*NHEAD*TSEQ*HDIM]; // tf32 bits
__device__ __align__(128) unsigned g_x32[(size_t)MROWS*CEMB];
__device__ __align__(128) unsigned g_y32[(size_t)MROWS*CEMB];
__device__ __align__(128) unsigned g_wa32[(size_t)CEMB*3*CEMB];
__device__ __align__(128) unsigned g_wp32[(size_t)CEMB*CEMB];
__device__ int4 g_lim[TSEQ];        // per-row prefix limits: (a, t, i, 0)

// ---------------------------------------------------------------------------
// helpers
// ---------------------------------------------------------------------------
__device__ __forceinline__ unsigned f2tf32(float x) {
    unsigned r;
    asm("cvt.rna.tf32.f32 %0, %1;" : "=r"(r) : "f"(x));
    return r;
}
__device__ __forceinline__ void mma_tf32(float* c, const unsigned* a, const unsigned* b) {
    asm volatile(
        "mma.sync.aligned.m16n8k8.row.col.f32.tf32.tf32.f32 "
        "{%0,%1,%2,%3}, {%4,%5,%6,%7}, {%8,%9}, {%0,%1,%2,%3};"
        : "+f"(c[0]), "+f"(c[1]), "+f"(c[2]), "+f"(c[3])
        : "r"(a[0]), "r"(a[1]), "r"(a[2]), "r"(a[3]), "r"(b[0]), "r"(b[1]));
}

// ---------------------------------------------------------------------------
// Elementwise f32 -> tf32-bits pre-conversion (dst = device symbol via sel)
// ---------------------------------------------------------------------------
__global__ void cvt_tf32(const float* __restrict__ src, int sel, int n4) {
    unsigned* dst = (sel == 0) ? g_x32 : (sel == 1) ? g_wa32 : g_wp32;
    int i = blockIdx.x * blockDim.x + threadIdx.x;
    if (i >= n4) return;
    float4 v = *(const float4*)&src[i * 4];
    uint4 o;
    o.x = f2tf32(v.x); o.y = f2tf32(v.y);
    o.z = f2tf32(v.z); o.w = f2tf32(v.w);
    *(uint4*)&dst[i * 4] = o;
}

// ---------------------------------------------------------------------------
// Row prefix limits (mask = union of 3 per-row segment prefixes).
// ---------------------------------------------------------------------------
__global__ void row_limits(const unsigned char* __restrict__ raw) {
    const int q = blockIdx.x;
    const int tid = threadIdx.x;
    const unsigned char b0 = raw[0], b1 = raw[1];
    const int mode = (b1 == 1) ? 0 : (b0 == 1) ? 1 : 2;

    int c0 = 0, c1 = 0, c2 = 0;
    for (int k = tid; k < TSEQ; k += 256) {
        size_t idx = (size_t)q * TSEQ + k;
        int v;
        if (mode == 0)      v = raw[idx] != 0;
        else if (mode == 1) v = ((const int*)raw)[idx] != 0;
        else                v = ((const float*)raw)[idx] != 0.0f;
        if (k < SEG1)      c0 += v;
        else if (k < SEG2) c1 += v;
        else               c2 += v;
    }
    __shared__ int s0, s1, s2;
    if (tid == 0) { s0 = 0; s1 = 0; s2 = 0; }
    __syncthreads();
#pragma unroll
    for (int off = 16; off; off >>= 1) {
        c0 += __shfl_xor_sync(0xffffffffu, c0, off);
        c1 += __shfl_xor_sync(0xffffffffu, c1, off);
        c2 += __shfl_xor_sync(0xffffffffu, c2, off);
    }
    if ((tid & 31) == 0) {
        atomicAdd(&s0, c0); atomicAdd(&s1, c1); atomicAdd(&s2, c2);
    }
    __syncthreads();
    if (tid == 0) g_lim[q] = make_int4(s0, SEG1 + s1, SEG2 + s2, 0);
}

// ---------------------------------------------------------------------------
// cp.async-pipelined tf32 GEMM (R11 known good). Scatter epilogue now emits
// K and V as tf32 BITS (converted once per element; attention reads bits).
// ---------------------------------------------------------------------------
template<bool SCATTER>
__global__ __launch_bounds__(256) void gemm_cp(float* __restrict__ out) {
    const unsigned* __restrict__ A = SCATTER ? g_x32 : g_y32;
    const unsigned* __restrict__ W = SCATTER ? g_wa32 : g_wp32;
    constexpr int LDB = SCATTER ? 3 * CEMB : CEMB;
    constexpr int ASTG = 128 * SAQ;
    constexpr int BSTG = 16 * SBQ;

    extern __shared__ unsigned smg[];
    unsigned* As0 = smg;
    unsigned* Bs0 = smg + 3 * ASTG;

    const int m0 = blockIdx.y * 128;
    const int n0 = blockIdx.x * 128;
    const int tid = threadIdx.x;
    const int lane = tid & 31;
    const int warp = tid >> 5;
    const int wm = (warp & 3) * 32;
    const int wn = (warp >> 2) * 64;
    const int fr = lane >> 2;
    const int fc = lane & 3;

    float acc[2][8][4];
#pragma unroll
    for (int mf = 0; mf < 2; mf++)
#pragma unroll
        for (int nf = 0; nf < 8; nf++)
#pragma unroll
            for (int r = 0; r < 4; r++) acc[mf][nf][r] = 0.f;

#define STAGE(kt_, buf_)                                                       \
    {                                                                          \
        const int k0_ = (kt_) * 16;                                            \
        _Pragma("unroll")                                                      \
        for (int u = 0; u < 2; u++) {                                          \
            int ia = tid + u * 256;                                            \
            int arow = ia >> 2, ac4 = (ia & 3) * 4;                            \
            int gm = m0 + arow;                                                \
            int apred = (gm < MROWS) ? 16 : 0;                                 \
            int gmc = gm < MROWS ? gm : MROWS - 1;                             \
            const unsigned* asrc = &A[(size_t)gmc * CEMB + k0_ + ac4];         \
            unsigned adst = (unsigned)__cvta_generic_to_shared(                \
                                &As0[(buf_) * ASTG + arow * SAQ + ac4]);       \
            asm volatile("cp.async.cg.shared.global [%0], [%1], 16, %2;"       \
                         :: "r"(adst), "l"(asrc), "r"(apred));                 \
            int ib = tid + u * 256;                                            \
            int brow = ib >> 5, bc4 = (ib & 31) * 4;                           \
            const unsigned* bsrc = &W[(size_t)(k0_ + brow) * LDB + n0 + bc4];  \
            unsigned bdst = (unsigned)__cvta_generic_to_shared(                \
                                &Bs0[(buf_) * BSTG + brow * SBQ + bc4]);       \
            asm volatile("cp.async.cg.shared.global [%0], [%1], 16;"           \
                         :: "r"(bdst), "l"(bsrc));                             \
        }                                                                      \
    }

    STAGE(0, 0);
    asm volatile("cp.async.commit_group;");
    STAGE(1, 1);
    asm volatile("cp.async.commit_group;");

    const int NK = CEMB / 16;  // 48
    for (int kt = 0; kt < NK; kt++) {
        asm volatile("cp.async.wait_group 1;");
        __syncthreads();

        if (kt + 2 < NK) STAGE(kt + 2, (kt + 2) % 3);
        asm volatile("cp.async.commit_group;");

        const unsigned* Asb = &As0[(kt % 3) * ASTG];
        const unsigned* Bsb = &Bs0[(kt % 3) * BSTG];
#pragma unroll
        for (int ks = 0; ks < 2; ks++) {
            const int kb = ks * 8;
            unsigned af[2][4], bf[8][2];
#pragma unroll
            for (int mf = 0; mf < 2; mf++) {
                af[mf][0] = Asb[(wm + mf * 16 + fr)     * SAQ + kb + fc];
                af[mf][1] = Asb[(wm + mf * 16 + fr + 8) * SAQ + kb + fc];
                af[mf][2] = Asb[(wm + mf * 16 + fr)     * SAQ + kb + fc + 4];
                af[mf][3] = Asb[(wm + mf * 16 + fr + 8) * SAQ + kb + fc + 4];
            }
#pragma unroll
            for (int nf = 0; nf < 8; nf++) {
                bf[nf][0] = Bsb[(kb + fc)     * SBQ + wn + nf * 8 + fr];
                bf[nf][1] = Bsb[(kb + fc + 4) * SBQ + wn + nf * 8 + fr];
            }
#pragma unroll
            for (int mf = 0; mf < 2; mf++)
#pragma unroll
                for (int nf = 0; nf < 8; nf++)
                    mma_tf32(acc[mf][nf], af[mf], bf[nf]);
        }
    }
#undef STAGE

    if (SCATTER) {
#pragma unroll
        for (int mf = 0; mf < 2; mf++)
#pragma unroll
            for (int nf = 0; nf < 8; nf++)
#pragma unroll
                for (int rg = 0; rg < 4; rg++) {
                    int m = m0 + wm + mf * 16 + fr + ((rg >= 2) ? 8 : 0);
                    if (m >= MROWS) continue;
                    int n = n0 + wn + nf * 8 + 2 * fc + (rg & 1);
                    int bb = m / TSEQ;
                    int t  = m - bb * TSEQ;
                    int which = n / CEMB;
                    int rem = n - which * CEMB;
                    int h = rem >> 6, d = rem & 63;
                    size_t idx = ((((size_t)bb * NHEAD + h) * TSEQ + t) << 6) + d;
                    if (which == 0)      g_q[idx]   = acc[mf][nf][rg];
                    else if (which == 1) g_k32[idx] = f2tf32(acc[mf][nf][rg]);
                    else                 g_v32[idx] = f2tf32(acc[mf][nf][rg]);
                }
    } else {
#pragma unroll
        for (int mf = 0; mf < 2; mf++)
#pragma unroll
            for (int nf = 0; nf < 8; nf++) {
                int n  = n0 + wn + nf * 8 + 2 * fc;
                int m1 = m0 + wm + mf * 16 + fr;
                if (m1 < MROWS)
                    *(float2*)&out[(size_t)m1 * CEMB + n] =
                        make_float2(acc[mf][nf][0], acc[mf][nf][1]);
                int m2 = m1 + 8;
                if (m2 < MROWS)
                    *(float2*)&out[(size_t)m2 * CEMB + n] =
                        make_float2(acc[mf][nf][2], acc[mf][nf][3]);
            }
    }
}

// ---------------------------------------------------------------------------
// Flash attention v6 = R11 v4 with K/V staged as pre-converted tf32 bits:
// fragment loads are plain LDS (zero in-loop cvt for K and V).
// ---------------------------------------------------------------------------
__global__ __launch_bounds__(128) void attn_v6() {
    extern __shared__ unsigned sm6[];
    unsigned* Kbuf[2] = { sm6,                sm6 + 64 * 68 };
    unsigned* Vbuf[2] = { sm6 + 2 * 64 * 68,  sm6 + 2 * 64 * 68 + 64 * 72 };
    __shared__ int s_ktmax;

    const int qt = blockIdx.x, h = blockIdx.y, b = blockIdx.z;
    const int q0 = qt * 64;
    const int tid = threadIdx.x, lane = tid & 31, warp = tid >> 5;
    const int fr = lane >> 2, fc = lane & 3;
    const int ra = warp * 16 + fr, rb = ra + 8;
    const int qa = q0 + ra, qb = q0 + rb;
    const size_t bh = ((size_t)b * NHEAD + h) * TSEQ;

    int4 La = make_int4(0, 0, 0, 0), Lb = La;
    if (qa < TSEQ) La = g_lim[qa];
    if (qb < TSEQ) Lb = g_lim[qb];

    if (warp == 0) {
        int q1 = q0 + lane, q2 = q0 + 32 + lane;
        int il = 0;
        if (q1 < TSEQ) il = g_lim[q1].z;
        if (q2 < TSEQ) il = max(il, g_lim[q2].z);
#pragma unroll
        for (int off = 16; off; off >>= 1)
            il = max(il, __shfl_xor_sync(0xffffffffu, il, off));
        if (lane == 0) s_ktmax = (il + 63) >> 6;
    }

    unsigned qf[8][4];
    {
        const float* Qa = &g_q[(bh + qa) * 64];
        const float* Qb = &g_q[(bh + qb) * 64];
#pragma unroll
        for (int ks = 0; ks < 8; ks++) {
            float x0 = (qa < TSEQ) ? Qa[8 * ks + fc]     : 0.f;
            float x1 = (qb < TSEQ) ? Qb[8 * ks + fc]     : 0.f;
            float x2 = (qa < TSEQ) ? Qa[8 * ks + fc + 4] : 0.f;
            float x3 = (qb < TSEQ) ? Qb[8 * ks + fc + 4] : 0.f;
            qf[ks][0] = f2tf32(x0 * 0.125f);
            qf[ks][1] = f2tf32(x1 * 0.125f);
            qf[ks][2] = f2tf32(x2 * 0.125f);
            qf[ks][3] = f2tf32(x3 * 0.125f);
        }
    }
    __syncthreads();
    const int ktmax = s_ktmax;

#define STAGE(kt_, buf_)                                                       \
    {                                                                          \
        const int k0_ = (kt_) * 64;                                            \
        for (int i = tid; i < 64 * 16; i += 128) {                             \
            int row = i >> 4, dc = (i & 15) * 4;                               \
            int kk2 = k0_ + row;                                               \
            int pred = (kk2 < TSEQ) ? 16 : 0;                                  \
            int kk2c = kk2 < TSEQ ? kk2 : TSEQ - 1;                            \
            const unsigned* gk = &g_k32[(bh + kk2c) * 64 + dc];                \
            const unsigned* gv = &g_v32[(bh + kk2c) * 64 + dc];                \
            unsigned dk = (unsigned)__cvta_generic_to_shared(                  \
                              &Kbuf[buf_][row * 68 + dc]);                     \
            unsigned dv = (unsigned)__cvta_generic_to_shared(                  \
                              &Vbuf[buf_][row * 72 + dc]);                     \
            asm volatile("cp.async.cg.shared.global [%0], [%1], 16, %2;"       \
                         :: "r"(dk), "l"(gk), "r"(pred));                      \
            asm volatile("cp.async.cg.shared.global [%0], [%1], 16, %2;"       \
                         :: "r"(dv), "l"(gv), "r"(pred));                      \
        }                                                                      \
    }

    STAGE(0, 0);
    asm volatile("cp.async.commit_group;");

    float o[8][4];
#pragma unroll
    for (int nf = 0; nf < 8; nf++)
#pragma unroll
        for (int r = 0; r < 4; r++) o[nf][r] = 0.f;
    float m_a = -1e30f, m_b = -1e30f, l_a = 0.f, l_b = 0.f;

    for (int kt = 0; kt < ktmax; kt++) {
        const int k0 = kt * 64;
        const int cur = kt & 1;

        if (kt + 1 < ktmax) STAGE(kt + 1, cur ^ 1);
        asm volatile("cp.async.commit_group;");
        asm volatile("cp.async.wait_group 1;");
        __syncthreads();

        const unsigned* Kc = Kbuf[cur];
        const unsigned* Vc = Vbuf[cur];

        float sacc[8][4];
#pragma unroll
        for (int nf = 0; nf < 8; nf++)
#pragma unroll
            for (int r = 0; r < 4; r++) sacc[nf][r] = 0.f;
#pragma unroll
        for (int ks = 0; ks < 8; ks++) {
            int kk = ks * 8;
#pragma unroll
            for (int nf = 0; nf < 8; nf++) {
                unsigned bf[2];
                bf[0] = Kc[(nf * 8 + fr) * 68 + kk + fc];
                bf[1] = Kc[(nf * 8 + fr) * 68 + kk + fc + 4];
                mma_tf32(sacc[nf], qf[ks], bf);
            }
        }

        float pma = -1e30f, pmb = -1e30f;
        const bool imgonly = (k0 >= SEG2);
#pragma unroll
        for (int nf = 0; nf < 8; nf++) {
            int kc0 = k0 + nf * 8 + 2 * fc;
            int kc1 = kc0 + 1;
            int la0, la1, lb0, lb1;
            if (imgonly) {
                la0 = La.z; la1 = La.z; lb0 = Lb.z; lb1 = Lb.z;
            } else {
                la0 = kc0 < SEG1 ? La.x : kc0 < SEG2 ? La.y : La.z;
                la1 = kc1 < SEG1 ? La.x : kc1 < SEG2 ? La.y : La.z;
                lb0 = kc0 < SEG1 ? Lb.x : kc0 < SEG2 ? Lb.y : Lb.z;
                lb1 = kc1 < SEG1 ? Lb.x : kc1 < SEG2 ? Lb.y : Lb.z;
            }
            sacc[nf][0] = (kc0 < la0) ? sacc[nf][0] : -1e30f;
            sacc[nf][1] = (kc1 < la1) ? sacc[nf][1] : -1e30f;
            sacc[nf][2] = (kc0 < lb0) ? sacc[nf][2] : -1e30f;
            sacc[nf][3] = (kc1 < lb1) ? sacc[nf][3] : -1e30f;
            pma = fmaxf(pma, fmaxf(sacc[nf][0], sacc[nf][1]));
            pmb = fmaxf(pmb, fmaxf(sacc[nf][2], sacc[nf][3]));
        }
        pma = fmaxf(pma, __shfl_xor_sync(0xffffffffu, pma, 1));
        pma = fmaxf(pma, __shfl_xor_sync(0xffffffffu, pma, 2));
        pmb = fmaxf(pmb, __shfl_xor_sync(0xffffffffu, pmb, 1));
        pmb = fmaxf(pmb, __shfl_xor_sync(0xffffffffu, pmb, 2));

        const float mna = fmaxf(m_a, pma), mnb = fmaxf(m_b, pmb);
        const float ala = __expf(m_a - mna), alb = __expf(m_b - mnb);
        m_a = mna; m_b = mnb;

        float psa = 0.f, psb = 0.f;
#pragma unroll
        for (int nf = 0; nf < 8; nf++) {
            float p0 = sacc[nf][0] > -5e29f ? __expf(sacc[nf][0] - mna) : 0.f;
            float p1 = sacc[nf][1] > -5e29f ? __expf(sacc[nf][1] - mna) : 0.f;
            float p2 = sacc[nf][2] > -5e29f ? __expf(sacc[nf][2] - mnb) : 0.f;
            float p3 = sacc[nf][3] > -5e29f ? __expf(sacc[nf][3] - mnb) : 0.f;
            sacc[nf][0] = p0; sacc[nf][1] = p1;
            sacc[nf][2] = p2; sacc[nf][3] = p3;
            psa += p0 + p1; psb += p2 + p3;
        }
        psa += __shfl_xor_sync(0xffffffffu, psa, 1);
        psa += __shfl_xor_sync(0xffffffffu, psa, 2);
        psb += __shfl_xor_sync(0xffffffffu, psb, 1);
        psb += __shfl_xor_sync(0xffffffffu, psb, 2);
        l_a = l_a * ala + psa;
        l_b = l_b * alb + psb;
#pragma unroll
        for (int nf = 0; nf < 8; nf++) {
            o[nf][0] *= ala; o[nf][1] *= ala;
            o[nf][2] *= alb; o[nf][3] *= alb;
        }

        const unsigned FULL = 0xffffffffu;
        const int src  = fr * 4 + (fc >> 1);
        const int src2 = src + 2;
        const bool oddc = (fc & 1);
#pragma unroll
        for (int ks = 0; ks < 8; ks++) {
            float c0 = sacc[ks][0], c1 = sacc[ks][1];
            float c2 = sacc[ks][2], c3 = sacc[ks][3];
            float v00 = __shfl_sync(FULL, c0, src),  v01 = __shfl_sync(FULL, c1, src);
            float v10 = __shfl_sync(FULL, c2, src),  v11 = __shfl_sync(FULL, c3, src);
            float v20 = __shfl_sync(FULL, c0, src2), v21 = __shfl_sync(FULL, c1, src2);
            float v30 = __shfl_sync(FULL, c2, src2), v31 = __shfl_sync(FULL, c3, src2);
            unsigned pa[4];
            pa[0] = f2tf32(oddc ? v01 : v00);
            pa[1] = f2tf32(oddc ? v11 : v10);
            pa[2] = f2tf32(oddc ? v21 : v20);
            pa[3] = f2tf32(oddc ? v31 : v30);
            int kk = ks * 8;
#pragma unroll
            for (int nf = 0; nf < 8; nf++) {
                unsigned bf[2];
                bf[0] = Vc[(kk + fc) * 72 + nf * 8 + fr];
                bf[1] = Vc[(kk + fc + 4) * 72 + nf * 8 + fr];
                mma_tf32(o[nf], pa, bf);
            }
        }
        __syncthreads();
    }
#undef STAGE

    // Epilogue: normalize; write tf32 bits into g_y32 (consumed by proj GEMM)
    const float inva = l_a > 0.f ? 1.f / l_a : 0.f;
    const float invb = l_b > 0.f ? 1.f / l_b : 0.f;
#pragma unroll
    for (int nf = 0; nf < 8; nf++) {
        int d = h * 64 + nf * 8 + 2 * fc;
        if (qa < TSEQ) {
            uint2 t;
            t.x = f2tf32(o[nf][0] * inva);
            t.y = f2tf32(o[nf][1] * inva);
            *(uint2*)&g_y32[((size_t)b * TSEQ + qa) * CEMB + d] = t;
        }
        if (qb < TSEQ) {
            uint2 t;
            t.x = f2tf32(o[nf][2] * invb);
            t.y = f2tf32(o[nf][3] * invb);
            *(uint2*)&g_y32[((size_t)b * TSEQ + qb) * CEMB + d] = t;
        }
    }
}

// ---------------------------------------------------------------------------
extern "C" void kernel_launch(void* const* d_in, const int* in_sizes, int n_in,
                              void* d_out, int out_size) {
    const float* x  = (const float*)d_in[0];
    const float* Wa = (const float*)d_in[1];
    const float* Wp = (const float*)d_in[2];
    const unsigned char* mask_raw = (const unsigned char*)d_in[3];
    float* out = (float*)d_out;

    const int ATTN_SH = (2 * 64 * 68 + 2 * 64 * 72) * 4;            // 71680
    const int GEMM_SH = (3 * 128 * SAQ + 3 * 16 * SBQ) * 4;         // 56832
    cudaFuncSetAttribute(attn_v6, cudaFuncAttributeMaxDynamicSharedMemorySize, ATTN_SH);
    cudaFuncSetAttribute(gemm_cp<true>,  cudaFuncAttributeMaxDynamicSharedMemorySize, GEMM_SH);
    cudaFuncSetAttribute(gemm_cp<false>, cudaFuncAttributeMaxDynamicSharedMemorySize, GEMM_SH);

    row_limits<<<TSEQ, 256>>>(mask_raw);

    {
        int n4x = MROWS * CEMB / 4;
        int n4a = CEMB * 3 * CEMB / 4;
        int n4p = CEMB * CEMB / 4;
        cvt_tf32<<<(n4x + 255) / 256, 256>>>(x,  0, n4x);
        cvt_tf32<<<(n4a + 255) / 256, 256>>>(Wa, 1, n4a);
        cvt_tf32<<<(n4p + 255) / 256, 256>>>(Wp, 2, n4p);
    }

    dim3 g1(3 * CEMB / 128, (MROWS + 127) / 128);   // (18, 54)
    gemm_cp<true><<<g1, 256, GEMM_SH>>>(nullptr);

    dim3 g2(KTILES, NHEAD, BATCH);                  // (27, 12, 4)
    attn_v6<<<g2, 128, ATTN_SH>>>();

    dim3 g3(CEMB / 128, (MROWS + 127) / 128);       // (6, 54)
    gemm_cp<false><<<g3, 256, GEMM_SH>>>(out);
}